// round 4
// baseline (speedup 1.0000x reference)
#include <cuda_runtime.h>

// Round 4: warp-specialized MeanAggregator.
//   producers (warps 0-3): stream neighbors of tile t+GRID into smem cat tile
//   consumers (warps 4-7): k-paired FFMA2 GEMM of tile t against interleaved w
// Pre-pass kernel interleaves w so the consumer's f32x2 pairs load directly.

#define N_NODES 50000
#define S_NEIGH 25
#define DIM     128
#define OUTD    128
#define KDIM    256
#define TM      32
#define THREADS 256
#define A_STRIDE 260            // floats per tile row (pad, 16B-aligned)
#define NT      3125            // 2*N_NODES / TM
#define GRID    296             // 2 persistent blocks per SM

// interleaved weights: wi[k2][2c+e] = w[2*k2+e][c]  (k2=0..127, c=0..127, e=0..1)
__device__ float g_wi[(KDIM / 2) * (2 * OUTD)];

// ---- packed f32x2 helpers ----
__device__ __forceinline__ unsigned long long fadd2(unsigned long long a, unsigned long long b) {
    unsigned long long d;
    asm("add.rn.f32x2 %0, %1, %2;" : "=l"(d) : "l"(a), "l"(b));
    return d;
}
__device__ __forceinline__ unsigned long long fmul2(unsigned long long a, unsigned long long b) {
    unsigned long long d;
    asm("mul.rn.f32x2 %0, %1, %2;" : "=l"(d) : "l"(a), "l"(b));
    return d;
}
__device__ __forceinline__ unsigned long long ffma2(unsigned long long a, unsigned long long b,
                                                    unsigned long long c) {
    unsigned long long d;
    asm("fma.rn.f32x2 %0, %1, %2, %3;" : "=l"(d) : "l"(a), "l"(b), "l"(c));
    return d;
}
__device__ __forceinline__ ulonglong2 ldcs16(const float* p) {
    ulonglong2 v;
    asm volatile("ld.global.cs.v2.u64 {%0, %1}, [%2];" : "=l"(v.x), "=l"(v.y) : "l"(p));
    return v;
}
__device__ __forceinline__ ulonglong2 ldg16u(const float* p) {
    return *reinterpret_cast<const ulonglong2*>(p);
}
__device__ __forceinline__ unsigned long long lds8(const float* p) {
    return *reinterpret_cast<const unsigned long long*>(p);
}

// ---- pre-pass: interleave w ----
__global__ void interleave_w(const float* __restrict__ w) {
    // out[k2*256 + c*2 + e] = w[(2*k2+e)*128 + c]
    const int i = blockIdx.x * blockDim.x + threadIdx.x;   // over 32768 outputs
    const int k2 = i >> 8;
    const int ce = i & 255;
    const int c  = ce >> 1;
    const int e  = ce & 1;
    g_wi[i] = w[(2 * k2 + e) * OUTD + c];
}

// ---- producer: build cat tile rows [x | mean(neg)] ----
__device__ __forceinline__ void produce_tile(
    float* __restrict__ Adst, int tile,
    const float* __restrict__ src, const float* __restrict__ src_neg,
    const float* __restrict__ dst, const float* __restrict__ dst_neg,
    int ptid, int pthreads, unsigned long long inv2)
{
    const long t0 = (long)tile * TM;
    for (int i = ptid; i < TM * (DIM / 4); i += pthreads) {
        const int r  = i >> 5;
        const int d4 = (i & 31) << 2;
        const long task = t0 + r;

        const float* xp; const float* np;
        if (task < N_NODES) {
            xp = src + task * DIM;
            np = src_neg + task * (long)(S_NEIGH * DIM);
        } else {
            const long rr = task - N_NODES;
            xp = dst + rr * DIM;
            np = dst_neg + rr * (long)(S_NEIGH * DIM);
        }

        unsigned long long s0 = 0ull, s1 = 0ull;
        const float* p = np + d4;
        #pragma unroll
        for (int j = 0; j < S_NEIGH; j++) {
            const ulonglong2 v = ldcs16(p + j * DIM);
            s0 = fadd2(s0, v.x);
            s1 = fadd2(s1, v.y);
        }
        const ulonglong2 xv = *reinterpret_cast<const ulonglong2*>(xp + d4);

        ulonglong2 m;
        m.x = fmul2(s0, inv2);
        m.y = fmul2(s1, inv2);

        *reinterpret_cast<ulonglong2*>(Adst + r * A_STRIDE + d4)       = xv;
        *reinterpret_cast<ulonglong2*>(Adst + r * A_STRIDE + DIM + d4) = m;
    }
}

__global__ __launch_bounds__(THREADS, 2)
void magg_kernel(const float* __restrict__ src,
                 const float* __restrict__ src_neg,
                 const float* __restrict__ dst,
                 const float* __restrict__ dst_neg,
                 float* __restrict__ out)
{
    __shared__ float A[2][TM][A_STRIDE];   // 66.6 KB double buffer

    const int tid  = threadIdx.x;
    const int wid  = tid >> 5;
    const int lane = tid & 31;

    unsigned long long inv2;
    asm("mov.b64 %0, {%1, %1};" : "=l"(inv2) : "f"(1.0f / (float)S_NEIGH));

    produce_tile(&A[0][0][0], blockIdx.x, src, src_neg, dst, dst_neg,
                 tid, THREADS, inv2);
    __syncthreads();

    int buf = 0;
    for (int t = blockIdx.x; t < NT; t += GRID) {
        const int nxt = t + GRID;

        if (wid < 4) {
            // -------- producers: build tile t+GRID --------
            if (nxt < NT) {
                produce_tile(&A[buf ^ 1][0][0], nxt, src, src_neg, dst, dst_neg,
                             tid, 128, inv2);
            }
        } else {
            // -------- consumers: k-paired FFMA2 GEMM of tile t --------
            // warp cw: rows 8cw..8cw+7; lane: cols 4*lane..4*lane+3
            const int cw = wid - 4;
            const int r0 = cw << 3;
            const int c0 = lane << 2;
            const float* Ab = &A[buf][0][0];
            const float* wip = g_wi + (c0 << 1);   // + k2*256 per step

            // acc[j][cc] : f32x2 {sum over even k, sum over odd k}
            unsigned long long acc[8][4];
            #pragma unroll
            for (int j = 0; j < 8; j++)
                #pragma unroll
                for (int cc = 0; cc < 4; cc++) acc[j][cc] = 0ull;

            #pragma unroll 4
            for (int k2 = 0; k2 < KDIM / 2; k2++) {
                // packed w pairs for this thread's 4 cols: 8 floats, coalesced
                const ulonglong2 wv0 = ldg16u(wip + (k2 << 8));
                const ulonglong2 wv1 = ldg16u(wip + (k2 << 8) + 4);
                const unsigned long long wp[4] = { wv0.x, wv0.y, wv1.x, wv1.y };

                #pragma unroll
                for (int j = 0; j < 8; j++) {
                    // {A[r][2k2], A[r][2k2+1]} — adjacent in smem, broadcast
                    const unsigned long long ap = lds8(Ab + (r0 + j) * A_STRIDE + (k2 << 1));
                    #pragma unroll
                    for (int cc = 0; cc < 4; cc++)
                        acc[j][cc] = ffma2(ap, wp[cc], acc[j][cc]);
                }
            }

            // fold {even,odd} partial sums and store
            const long row0 = (long)t * TM + r0;
            float* o = out + row0 * OUTD + c0;
            #pragma unroll
            for (int j = 0; j < 8; j++) {
                float4 r;
                #pragma unroll
                for (int cc = 0; cc < 4; cc++) {
                    float lo, hi;
                    asm("mov.b64 {%0, %1}, %2;" : "=f"(lo), "=f"(hi) : "l"(acc[j][cc]));
                    (&r.x)[cc] = lo + hi;
                }
                *reinterpret_cast<float4*>(o + (long)j * OUTD) = r;
            }
        }

        __syncthreads();
        buf ^= 1;
    }
}

extern "C" void kernel_launch(void* const* d_in, const int* in_sizes, int n_in,
                              void* d_out, int out_size)
{
    const float* src     = (const float*)d_in[0];
    const float* src_neg = (const float*)d_in[1];
    const float* dst     = (const float*)d_in[2];
    const float* dst_neg = (const float*)d_in[3];
    const float* w       = (const float*)d_in[4];
    float* out = (float*)d_out;

    interleave_w<<<(KDIM / 2) * (2 * OUTD) / 256, 256>>>(w);
    magg_kernel<<<GRID, THREADS>>>(src, src_neg, dst, dst_neg, out);
}

// round 5
// speedup vs baseline: 1.3278x; 1.3278x over previous
#include <cuda_runtime.h>

// Round 5: warp-specialized MeanAggregator, column-paired FFMA2 consumer.
//   producers (warps 0-3): stream neighbors of tile t+GRID into smem cat tile
//   consumers (warps 4-7): GEMM of tile t; f32x2 accumulators pair adjacent
//     OUTPUT COLUMNS, so w pairs load directly from the natural layout and
//     accumulator footprint stays at 32 regs (R3 level). fma-pipe ops halved.

#define N_NODES 50000
#define S_NEIGH 25
#define DIM     128
#define OUTD    128
#define KDIM    256
#define TM      32
#define THREADS 256
#define A_STRIDE 260            // floats per tile row (pad, 16B-aligned)
#define NT      3125            // 2*N_NODES / TM
#define GRID    296             // 2 persistent blocks per SM

typedef unsigned long long u64;

// ---- packed f32x2 helpers ----
__device__ __forceinline__ u64 fadd2(u64 a, u64 b) {
    u64 d; asm("add.rn.f32x2 %0, %1, %2;" : "=l"(d) : "l"(a), "l"(b)); return d;
}
__device__ __forceinline__ u64 fmul2(u64 a, u64 b) {
    u64 d; asm("mul.rn.f32x2 %0, %1, %2;" : "=l"(d) : "l"(a), "l"(b)); return d;
}
__device__ __forceinline__ u64 ffma2(u64 a, u64 b, u64 c) {
    u64 d; asm("fma.rn.f32x2 %0, %1, %2, %3;" : "=l"(d) : "l"(a), "l"(b), "l"(c)); return d;
}
__device__ __forceinline__ u64 bcast2(float x) {          // {x, x}
    u64 d; asm("mov.b64 %0, {%1, %1};" : "=l"(d) : "f"(x)); return d;
}
// 16B streaming load (evict-first; don't pollute caches with the 1.28GB stream)
__device__ __forceinline__ ulonglong2 ldcs16(const float* p) {
    ulonglong2 v;
    asm volatile("ld.global.cs.v2.u64 {%0, %1}, [%2];" : "=l"(v.x), "=l"(v.y) : "l"(p));
    return v;
}
__device__ __forceinline__ float4 ld4(const float* p) {
    return *reinterpret_cast<const float4*>(p);
}

// ---- producer: build cat tile rows [x | mean(neg)] ----
__device__ __forceinline__ void produce_tile(
    float* __restrict__ Adst, int tile,
    const float* __restrict__ src, const float* __restrict__ src_neg,
    const float* __restrict__ dst, const float* __restrict__ dst_neg,
    int ptid, int pthreads, u64 inv2)
{
    const long t0 = (long)tile * TM;
    for (int i = ptid; i < TM * (DIM / 4); i += pthreads) {
        const int r  = i >> 5;            // row 0..31
        const int d4 = (i & 31) << 2;     // feature chunk
        const long task = t0 + r;

        const float* xp; const float* np;
        if (task < N_NODES) {
            xp = src + task * DIM;
            np = src_neg + task * (long)(S_NEIGH * DIM);
        } else {
            const long rr = task - N_NODES;
            xp = dst + rr * DIM;
            np = dst_neg + rr * (long)(S_NEIGH * DIM);
        }

        u64 s0 = 0ull, s1 = 0ull;
        const float* p = np + d4;
        #pragma unroll
        for (int j = 0; j < S_NEIGH; j++) {
            const ulonglong2 v = ldcs16(p + j * DIM);
            s0 = fadd2(s0, v.x);
            s1 = fadd2(s1, v.y);
        }
        const ulonglong2 xv = *reinterpret_cast<const ulonglong2*>(xp + d4);

        ulonglong2 m;
        m.x = fmul2(s0, inv2);
        m.y = fmul2(s1, inv2);

        *reinterpret_cast<ulonglong2*>(Adst + r * A_STRIDE + d4)       = xv;
        *reinterpret_cast<ulonglong2*>(Adst + r * A_STRIDE + DIM + d4) = m;
    }
}

__global__ __launch_bounds__(THREADS, 2)
void magg_kernel(const float* __restrict__ src,
                 const float* __restrict__ src_neg,
                 const float* __restrict__ dst,
                 const float* __restrict__ dst_neg,
                 const float* __restrict__ w,
                 float* __restrict__ out)
{
    __shared__ float A[2][TM][A_STRIDE];   // 66.6 KB double buffer

    const int tid  = threadIdx.x;
    const int wid  = tid >> 5;
    const int lane = tid & 31;

    u64 inv2; asm("mov.b64 %0, {%1, %1};" : "=l"(inv2) : "f"(1.0f / (float)S_NEIGH));

    produce_tile(&A[0][0][0], blockIdx.x, src, src_neg, dst, dst_neg,
                 tid, THREADS, inv2);
    __syncthreads();

    int buf = 0;
    for (int t = blockIdx.x; t < NT; t += GRID) {
        const int nxt = t + GRID;

        if (wid < 4) {
            // -------- producers: build tile t+GRID --------
            if (nxt < NT) {
                produce_tile(&A[buf ^ 1][0][0], nxt, src, src_neg, dst, dst_neg,
                             tid, 128, inv2);
            }
        } else {
            // -------- consumers: column-paired FFMA2 GEMM of tile t --------
            // warp cw: rows 8cw..8cw+7; lane: cols 4*lane..4*lane+3 (2 pairs)
            const int cw = wid - 4;
            const int r0 = cw << 3;
            const int c0 = lane << 2;
            const float* Ab = &A[buf][0][0];

            // acc[j][cc] = {out[r0+j][c0+2cc], out[r0+j][c0+2cc+1]}
            u64 acc[8][2];
            #pragma unroll
            for (int j = 0; j < 8; j++) { acc[j][0] = 0ull; acc[j][1] = 0ull; }

            #pragma unroll 4
            for (int k4 = 0; k4 < KDIM / 4; k4++) {
                float4 a[8];
                #pragma unroll
                for (int j = 0; j < 8; j++)
                    a[j] = ld4(Ab + (r0 + j) * A_STRIDE + (k4 << 2));  // broadcast LDS.128

                #pragma unroll
                for (int kk = 0; kk < 4; kk++) {
                    // w[k][c0..c0+3] -> two packed column pairs, natural layout
                    const float4 wv = ld4(w + (long)((k4 << 2) + kk) * OUTD + c0);
                    const u64 wp0 = reinterpret_cast<const u64*>(&wv)[0];
                    const u64 wp1 = reinterpret_cast<const u64*>(&wv)[1];
                    #pragma unroll
                    for (int j = 0; j < 8; j++) {
                        const u64 ap = bcast2((&a[j].x)[kk]);   // ALU-pipe pack
                        acc[j][0] = ffma2(ap, wp0, acc[j][0]);  // fma-pipe, 2 cols
                        acc[j][1] = ffma2(ap, wp1, acc[j][1]);
                    }
                }
            }

            // accumulators already hold the output pairs -> direct 16B stores
            const long row0 = (long)t * TM + r0;
            float* o = out + row0 * OUTD + c0;
            #pragma unroll
            for (int j = 0; j < 8; j++) {
                ulonglong2 r; r.x = acc[j][0]; r.y = acc[j][1];
                *reinterpret_cast<ulonglong2*>(o + (long)j * OUTD) = r;
            }
        }

        __syncthreads();
        buf ^= 1;
    }
}

extern "C" void kernel_launch(void* const* d_in, const int* in_sizes, int n_in,
                              void* d_out, int out_size)
{
    const float* src     = (const float*)d_in[0];
    const float* src_neg = (const float*)d_in[1];
    const float* dst     = (const float*)d_in[2];
    const float* dst_neg = (const float*)d_in[3];
    const float* w       = (const float*)d_in[4];
    float* out = (float*)d_out;

    magg_kernel<<<GRID, THREADS>>>(src, src_neg, dst, dst_neg, w, out);
}